// round 3
// baseline (speedup 1.0000x reference)
#include <cuda_runtime.h>
#include <cstdint>
#include <cstddef>

namespace {
constexpr int T = 1000, B = 256, I = 700, H = 256, O = 20, WHS = I + H;
constexpr float DELTA = 0.01f, GAMMA = 0.9f, THETA = 1.0f;
constexpr size_t OFF_LOSS = (size_t)T * B * O;
constexpr size_t OFF_ZF = OFF_LOSS + 1;
constexpr size_t OFF_UF = OFF_ZF + (size_t)B * H;
constexpr size_t OFF_OUF = OFF_UF + (size_t)B * H;
// shared memory layout (float offsets) for the recurrence kernel
constexpr int SM_ZB = 0;                    // [2][256] float4 z ring (j-major, 4 rows)
constexpr int SM_WS = 2048;                 // [256][128] W_z half: [j][h_local]
constexpr int SM_COMB = SM_WS + 32768;      // [4][128] cross-half matmul partials
constexpr int SM_WOT = SM_COMB + 512;       // [128][20] W_o half: [h_local][o]
constexpr int SM_POUA = SM_WOT + 2560;      // [2][80] rank0 readout partials (dbl buf)
constexpr int SM_POUB = SM_POUA + 160;      // [2][80] rank1 partials (landed via DSMEM)
constexpr int SM_OUS = SM_POUB + 160;       // [4][20] ou state
constexpr int SM_AL = SM_OUS + 80;          // [20] alpha
constexpr int SM_TOT = SM_AL + 32;
}  // namespace

__device__ float g_curx[(size_t)T * B * H];  // x @ W_x^T, [t*B+b][h]
__device__ float g_loss[B];                  // per-row loss partials

// ---------------------------------------------------------------------------
// Kernel 1: cur_x = x @ W_x^T  (fp32, 128x128x8 tiles, 8x8 per thread)
// ---------------------------------------------------------------------------
__global__ __launch_bounds__(256, 2) void gemm_curx_kernel(
    const float* __restrict__ X, const float* __restrict__ Wh) {
  __shared__ float As[8][128];
  __shared__ float Bs[8][128];
  const int tid = threadIdx.x;
  const int m0 = blockIdx.y * 128, n0 = blockIdx.x * 128;
  const int lrow = tid >> 1, lk = (tid & 1) << 2;
  const int tx = tid & 15, ty = tid >> 4;
  const float* aG = X + (size_t)(m0 + lrow) * I + lk;
  const float* bG = Wh + (size_t)(n0 + lrow) * WHS + lk;

  float acc[8][8];
#pragma unroll
  for (int i = 0; i < 8; ++i)
#pragma unroll
    for (int j = 0; j < 8; ++j) acc[i][j] = 0.f;

  for (int k0 = 0; k0 < I; k0 += 8) {
    float4 av = make_float4(0.f, 0.f, 0.f, 0.f);
    float4 bv = make_float4(0.f, 0.f, 0.f, 0.f);
    if (k0 + lk < I) {
      av = *reinterpret_cast<const float4*>(aG + k0);
      bv = *reinterpret_cast<const float4*>(bG + k0);
    }
    __syncthreads();
    As[lk + 0][lrow] = av.x; As[lk + 1][lrow] = av.y;
    As[lk + 2][lrow] = av.z; As[lk + 3][lrow] = av.w;
    Bs[lk + 0][lrow] = bv.x; Bs[lk + 1][lrow] = bv.y;
    Bs[lk + 2][lrow] = bv.z; Bs[lk + 3][lrow] = bv.w;
    __syncthreads();
#pragma unroll
    for (int kk = 0; kk < 8; ++kk) {
      float a[8], b[8];
      *reinterpret_cast<float4*>(a)     = *reinterpret_cast<const float4*>(&As[kk][ty * 8]);
      *reinterpret_cast<float4*>(a + 4) = *reinterpret_cast<const float4*>(&As[kk][ty * 8 + 4]);
      *reinterpret_cast<float4*>(b)     = *reinterpret_cast<const float4*>(&Bs[kk][tx * 8]);
      *reinterpret_cast<float4*>(b + 4) = *reinterpret_cast<const float4*>(&Bs[kk][tx * 8 + 4]);
#pragma unroll
      for (int i = 0; i < 8; ++i)
#pragma unroll
        for (int j = 0; j < 8; ++j) acc[i][j] += a[i] * b[j];
    }
  }
  float* C = g_curx + (size_t)(m0 + ty * 8) * H + n0 + tx * 8;
#pragma unroll
  for (int i = 0; i < 8; ++i) {
    *reinterpret_cast<float4*>(C + (size_t)i * H) =
        make_float4(acc[i][0], acc[i][1], acc[i][2], acc[i][3]);
    *reinterpret_cast<float4*>(C + (size_t)i * H + 4) =
        make_float4(acc[i][4], acc[i][5], acc[i][6], acc[i][7]);
  }
}

// ---------------------------------------------------------------------------
// cluster helpers
// ---------------------------------------------------------------------------
__device__ __forceinline__ void cluster_sync_all() {
  asm volatile("barrier.cluster.arrive.aligned;" ::: "memory");
  asm volatile("barrier.cluster.wait.aligned;" ::: "memory");
}
__device__ __forceinline__ unsigned smem_u32(const void* p) {
  return (unsigned)__cvta_generic_to_shared(p);
}
__device__ __forceinline__ unsigned mapa_rank(unsigned a, unsigned r) {
  unsigned o;
  asm("mapa.shared::cluster.u32 %0, %1, %2;" : "=r"(o) : "r"(a), "r"(r));
  return o;
}
__device__ __forceinline__ void stc_f32(unsigned a, float v) {
  asm volatile("st.shared::cluster.f32 [%0], %1;" :: "r"(a), "f"(v) : "memory");
}

// ---------------------------------------------------------------------------
// Kernel 2: persistent BRF recurrence, 64 clusters x 2 CTAs x 256 thr
// ---------------------------------------------------------------------------
__global__ void __cluster_dims__(2, 1, 1) __launch_bounds__(256, 1)
rec_kernel(const float* __restrict__ Wh, const float* __restrict__ omp,
           const float* __restrict__ bop, const float* __restrict__ Wo,
           const float* __restrict__ taup, const int* __restrict__ Y,
           float* __restrict__ out) {
  extern __shared__ float sm[];
  float4* zb = reinterpret_cast<float4*>(sm + SM_ZB);
  float* Ws = sm + SM_WS;
  float* comb = sm + SM_COMB;
  float* WoT = sm + SM_WOT;
  float* pouA = sm + SM_POUA;
  float* pouB = sm + SM_POUB;
  float* ous = sm + SM_OUS;
  float* alph = sm + SM_AL;

  const int tid = threadIdx.x;
  unsigned rank;
  asm("mov.u32 %0, %%cluster_ctarank;" : "=r"(rank));
  const int cl = blockIdx.x >> 1, row0 = cl * 4;

  // ---- init smem ----
  for (int i = tid; i < 32768; i += 256) {
    int j = i >> 7, hl = i & 127;
    Ws[i] = Wh[(size_t)((int)rank * 128 + hl) * WHS + I + j];
  }
  for (int i = tid; i < 2560; i += 256) {
    int hl = i / 20, o = i - hl * 20;
    WoT[i] = Wo[o * H + (int)rank * 128 + hl];
  }
  if (tid < O) alph[tid] = expf(-DELTA / taup[tid]);
  for (int i = tid; i < 512; i += 256) zb[i] = make_float4(0.f, 0.f, 0.f, 0.f);
  for (int i = tid; i < 160; i += 256) { pouA[i] = 0.f; pouB[i] = 0.f; }
  for (int i = tid; i < 80; i += 256) ous[i] = 0.f;

  const int h = tid & 127, half = tid >> 7;
  float om = 0.f, pom = 0.f, bof = 0.f;
  float u[4] = {0, 0, 0, 0}, v[4] = {0, 0, 0, 0}, q[4] = {0, 0, 0, 0},
        zr[4] = {0, 0, 0, 0};
  if (tid < 128) {
    int hg = (int)rank * 128 + tid;
    om = fabsf(omp[hg]);
    float dm = DELTA * om;
    pom = (-1.f + sqrtf(1.f - dm * dm)) / DELTA;
    bof = fabsf(bop[hg]);
  }
  float lossacc = 0.f;
  int yprev = 0;

  const unsigned zrem = mapa_rank(smem_u32(zb), rank ^ 1u);     // peer z ring
  const unsigned prem = mapa_rank(smem_u32(pouB), 0u);          // rank0 pouB

  __syncthreads();
  cluster_sync_all();

  for (int t = 0; t < T; ++t) {
    const int cb = t & 1, nb = cb ^ 1;

    // ---- readout of step t-1 (rank0, 4 threads; overlaps matmul of step t) ----
    if (rank == 0 && tid < 4) {
      int ynew = Y[t * B + row0 + tid];
      if (t > 0) {
        const int pb = cb ^ 1;
        const float* pa = pouA + pb * 80 + tid * 20;
        const float* pbp = pouB + pb * 80 + tid * 20;
        float m = -1e30f, ly = 0.f;
        for (int o = 0; o < O; ++o) {
          float a = alph[o];
          float s = ous[tid * 20 + o] * a + (1.f - a) * (pa[o] + pbp[o]);
          ous[tid * 20 + o] = s;
          out[(size_t)(t - 1) * B * O + (size_t)(row0 + tid) * O + o] = s;
          m = fmaxf(m, s);
          if (o == yprev) ly = s;
        }
        float se = 0.f;
        for (int o = 0; o < O; ++o) se += expf(ous[tid * 20 + o] - m);
        lossacc += -(ly - m - logf(se)) * (1.f / (float)B);
      }
      yprev = ynew;
    }

    // ---- prefetch input current for this step ----
    float c0 = 0.f, c1 = 0.f, c2 = 0.f, c3 = 0.f;
    if (tid < 128) {
      const float* cp = g_curx + ((size_t)t * B + row0) * H + (int)rank * 128 + tid;
      c0 = cp[0]; c1 = cp[H]; c2 = cp[2 * H]; c3 = cp[3 * H];
    }

    // ---- z_{t-1} @ W_z^T (this CTA's 128 h-outputs, inner dim split by half) ----
    float a0 = 0.f, a1 = 0.f, a2 = 0.f, a3 = 0.f;
    {
      const float4* zrow = zb + cb * 256 + half * 128;
      const float* wc = Ws + half * 128 * 128 + h;
#pragma unroll 16
      for (int j = 0; j < 128; ++j) {
        float w = wc[j * 128];       // lanes = consecutive h: conflict-free
        float4 z4 = zrow[j];         // broadcast LDS.128
        a0 += w * z4.x; a1 += w * z4.y; a2 += w * z4.z; a3 += w * z4.w;
      }
    }
    if (half) {
      comb[h] = a0; comb[128 + h] = a1; comb[256 + h] = a2; comb[384 + h] = a3;
    }
    __syncthreads();

    // ---- state update + spike + z exchange ----
    if (tid < 128) {
      float cw[4] = {c0 + a0 + comb[tid], c1 + a1 + comb[128 + tid],
                     c2 + a2 + comb[256 + tid], c3 + a3 + comb[384 + tid]};
#pragma unroll
      for (int r = 0; r < 4; ++r) {
        float b = pom - bof - q[r];
        float un = u[r] + DELTA * (b * u[r] - om * v[r] + cw[r]);
        float vn = v[r] + DELTA * (om * un + b * v[r]);
        float z = (un - THETA - q[r]) > 0.f ? 1.f : 0.f;
        q[r] = GAMMA * q[r] + z;
        u[r] = un; v[r] = vn; zr[r] = z;
      }
      int jg = (int)rank * 128 + tid;
      zb[nb * 256 + jg] = make_float4(zr[0], zr[1], zr[2], zr[3]);
      unsigned pa = zrem + (unsigned)(nb * 256 + jg) * 16u;
      stc_f32(pa, zr[0]); stc_f32(pa + 4, zr[1]);
      stc_f32(pa + 8, zr[2]); stc_f32(pa + 12, zr[3]);
    }
    __syncthreads();

    // ---- readout partials over this CTA's h-half (needs z_t) ----
    if (tid < 80) {
      int r = tid / 20, o = tid - r * 20;
      const float* zz = sm + SM_ZB + (size_t)(nb * 256 + (int)rank * 128) * 4 + r;
      float s = 0.f;
#pragma unroll 8
      for (int jj = 0; jj < 128; ++jj) s += zz[jj * 4] * WoT[jj * 20 + o];
      if (rank == 0) pouA[cb * 80 + tid] = s;
      else stc_f32(prem + (unsigned)(cb * 80 + tid) * 4u, s);
    }

    cluster_sync_all();  // releases z + pou DSMEM writes for step t
  }

  // ---- final readout (t = T-1) ----
  if (rank == 0 && tid < 4) {
    const int pb = (T - 1) & 1;
    const float* pa = pouA + pb * 80 + tid * 20;
    const float* pbp = pouB + pb * 80 + tid * 20;
    float m = -1e30f, ly = 0.f;
    for (int o = 0; o < O; ++o) {
      float a = alph[o];
      float s = ous[tid * 20 + o] * a + (1.f - a) * (pa[o] + pbp[o]);
      ous[tid * 20 + o] = s;
      out[(size_t)(T - 1) * B * O + (size_t)(row0 + tid) * O + o] = s;
      m = fmaxf(m, s);
      if (o == yprev) ly = s;
    }
    float se = 0.f;
    for (int o = 0; o < O; ++o) se += expf(ous[tid * 20 + o] - m);
    lossacc += -(ly - m - logf(se)) * (1.f / (float)B);
    g_loss[row0 + tid] = lossacc;
  }
  __syncthreads();

  if (tid < 128) {
#pragma unroll
    for (int r = 0; r < 4; ++r) {
      size_t idx = (size_t)(row0 + r) * H + (int)rank * 128 + tid;
      out[OFF_ZF + idx] = zr[r];
      out[OFF_UF + idx] = u[r];
    }
  }
  if (rank == 0 && tid < 80) {
    int r = tid / 20, o = tid - r * 20;
    out[OFF_OUF + (size_t)(row0 + r) * O + o] = ous[tid];
  }
}

// ---------------------------------------------------------------------------
// Kernel 3: deterministic loss reduction
// ---------------------------------------------------------------------------
__global__ void loss_sum_kernel(float* __restrict__ out) {
  __shared__ float s[256];
  s[threadIdx.x] = g_loss[threadIdx.x];
  __syncthreads();
  for (int st = 128; st > 0; st >>= 1) {
    if (threadIdx.x < st) s[threadIdx.x] += s[threadIdx.x + st];
    __syncthreads();
  }
  if (threadIdx.x == 0) out[OFF_LOSS] = s[0];
}

// ---------------------------------------------------------------------------
extern "C" void kernel_launch(void* const* d_in, const int* in_sizes, int n_in,
                              void* d_out, int out_size) {
  const float* x = (const float*)d_in[0];
  const int* y = (const int*)d_in[1];
  const float* Wh = (const float*)d_in[2];
  const float* omega = (const float*)d_in[3];
  const float* boff = (const float*)d_in[4];
  const float* Wo = (const float*)d_in[5];
  const float* tau = (const float*)d_in[6];
  float* out = (float*)d_out;

  cudaFuncSetAttribute(rec_kernel, cudaFuncAttributeMaxDynamicSharedMemorySize,
                       SM_TOT * (int)sizeof(float));

  gemm_curx_kernel<<<dim3(2, (T * B) / 128), 256>>>(x, Wh);
  rec_kernel<<<B / 2, 256, SM_TOT * sizeof(float)>>>(Wh, omega, boff, Wo, tau, y, out);
  loss_sum_kernel<<<1, 256>>>(out);
}

// round 5
// speedup vs baseline: 1.4137x; 1.4137x over previous
#include <cuda_runtime.h>
#include <cuda_bf16.h>
#include <cstdint>
#include <cstddef>

namespace {
constexpr int T = 1000, B = 256, I = 700, H = 256, O = 20, WHS = I + H;
constexpr float DELTA = 0.01f, GAMMA = 0.9f, THETA = 1.0f;
constexpr size_t OFF_LOSS = (size_t)T * B * O;
constexpr size_t OFF_ZF = OFF_LOSS + 1;
constexpr size_t OFF_UF = OFF_ZF + (size_t)B * H;
constexpr size_t OFF_OUF = OFF_UF + (size_t)B * H;

// ---- recurrence kernel smem layout (float offsets) ----
constexpr int SM_ZB = 0;
constexpr int SM_WS = 2048;
constexpr int SM_COMB = SM_WS + 32768;
constexpr int SM_WOT = SM_COMB + 512;
constexpr int SM_POUA = SM_WOT + 2560;
constexpr int SM_POUB = SM_POUA + 160;
constexpr int SM_OUS = SM_POUB + 160;
constexpr int SM_AL = SM_OUS + 80;
constexpr int SM_TOT = SM_AL + 32;

// ---- mma.sync GEMM config ----
constexpr int NCH = 22;                 // K chunks of 32 (K padded to 704)
constexpr int WIMG = 256 * 64;          // 16 KB: one (term,chunk) W image
// stage byte offsets (per 48 KB stage)
constexpr int AHI = 0;                  // [128 rows][64B] swizzled
constexpr int ALO = 8192;
constexpr int BHI = 16384;              // [256 rows][64B] swizzled
constexpr int BLO = 32768;
constexpr int STAGE = 49152;
constexpr int GS_TOTAL = 2 * STAGE;     // 96 KB
}  // namespace

__device__ float g_curx[(size_t)T * B * H];  // x @ W_x^T
__device__ float g_loss[B];
__device__ __align__(128) unsigned char g_wB[2 * NCH * WIMG];  // [term][chunk] images

// ---------------------------------------------------------------------------
// helpers
// ---------------------------------------------------------------------------
__device__ __forceinline__ unsigned smem_u32(const void* p) {
  return (unsigned)__cvta_generic_to_shared(p);
}
__device__ __forceinline__ void cluster_sync_all() {
  asm volatile("barrier.cluster.arrive.aligned;" ::: "memory");
  asm volatile("barrier.cluster.wait.aligned;" ::: "memory");
}
__device__ __forceinline__ unsigned mapa_rank(unsigned a, unsigned r) {
  unsigned o;
  asm("mapa.shared::cluster.u32 %0, %1, %2;" : "=r"(o) : "r"(a), "r"(r));
  return o;
}
__device__ __forceinline__ void stc_f32(unsigned a, float v) {
  asm volatile("st.shared::cluster.f32 [%0], %1;" :: "r"(a), "f"(v) : "memory");
}

#define LDSM4(r, addr)                                                        \
  asm volatile("ldmatrix.sync.aligned.m8n8.x4.shared.b16 {%0,%1,%2,%3}, [%4];" \
               : "=r"((r)[0]), "=r"((r)[1]), "=r"((r)[2]), "=r"((r)[3])        \
               : "r"(addr))

#define MMA16816(d, a, b0, b1)                                                \
  asm volatile(                                                               \
      "mma.sync.aligned.m16n8k16.row.col.f32.bf16.bf16.f32 "                  \
      "{%0,%1,%2,%3},{%4,%5,%6,%7},{%8,%9},{%0,%1,%2,%3};"                    \
      : "+f"((d)[0]), "+f"((d)[1]), "+f"((d)[2]), "+f"((d)[3])                \
      : "r"((a)[0]), "r"((a)[1]), "r"((a)[2]), "r"((a)[3]), "r"(b0), "r"(b1))

#define CPASYNC16(dst, src)                                                   \
  asm volatile("cp.async.cg.shared.global [%0], [%1], 16;" :: "r"(dst),       \
               "l"(src) : "memory")

// ---------------------------------------------------------------------------
// Kernel 0: split W_h[:, :700] into bf16 hi/lo, pre-swizzled smem-image layout
// image[n][cSw][8 bf16], cSw = c ^ ((n>>1)&3). One block per (term, chunk).
// ---------------------------------------------------------------------------
__global__ void prep_w_kernel(const float* __restrict__ Wh) {
  const int chunk = blockIdx.x % NCH;
  const int term = blockIdx.x / NCH;  // 0 = hi, 1 = lo
  const int n = threadIdx.x;          // 0..255
  unsigned char* dst = g_wB + (size_t)(term * NCH + chunk) * WIMG + n * 64;
#pragma unroll
  for (int c = 0; c < 4; ++c) {
    uint32_t u[4];
#pragma unroll
    for (int jj = 0; jj < 4; ++jj) {
      const int k = chunk * 32 + c * 8 + jj * 2;
      float w0 = (k < I) ? Wh[(size_t)n * WHS + k] : 0.f;
      float w1 = (k + 1 < I) ? Wh[(size_t)n * WHS + k + 1] : 0.f;
      __nv_bfloat16 h0 = __float2bfloat16(w0), h1 = __float2bfloat16(w1);
      if (term) {
        h0 = __float2bfloat16(w0 - __bfloat162float(h0));
        h1 = __float2bfloat16(w1 - __bfloat162float(h1));
      }
      u[jj] = (uint32_t)__bfloat16_as_ushort(h0) |
              ((uint32_t)__bfloat16_as_ushort(h1) << 16);
    }
    const int cSw = c ^ ((n >> 1) & 3);
    *reinterpret_cast<uint4*>(dst + cSw * 16) = make_uint4(u[0], u[1], u[2], u[3]);
  }
}

// ---------------------------------------------------------------------------
// Kernel 1: cur_x = x @ W_x^T via mma.sync bf16, 3-term hi/lo split.
// CTA: 128(M) x 256(N), 8 warps (2x4), warp tile 64x64, K chunks of 32.
// ---------------------------------------------------------------------------
__global__ __launch_bounds__(256, 1) void gemm_mma_kernel(const float* __restrict__ X) {
  extern __shared__ __align__(1024) unsigned char smem[];
  const uint32_t sb = smem_u32(smem);
  const int tid = threadIdx.x;
  const int lane = tid & 31, wid = tid >> 5;
  const int wm = (wid & 1) * 64, wn = (wid >> 1) * 64;
  const int m0 = blockIdx.x * 128;

  // A loader mapping: row = tid>>1 (0..127), kseg = (tid&1)*16
  const int arow = tid >> 1;
  const int aseg = (tid & 1) << 4;
  const float* xrow = X + (size_t)(m0 + arow) * I;
  const uint32_t aXor = ((arow >> 1) & 3);
  const uint32_t aDstBase = (uint32_t)(arow * 64);

  // per-lane ldmatrix address components
  int raddr[4], sxa[4], rbad[4], sxb[4];
#pragma unroll
  for (int mt = 0; mt < 4; ++mt) {
    int r = wm + mt * 16 + (lane & 15);
    raddr[mt] = r * 64;
    sxa[mt] = (r >> 1) & 3;
  }
  const int ca = lane >> 4;
#pragma unroll
  for (int g = 0; g < 4; ++g) {
    int n = wn + g * 16 + (lane & 7) + ((lane >> 4) << 3);
    rbad[g] = n * 64;
    sxb[g] = (n >> 1) & 3;
  }
  const int cb = (lane >> 3) & 1;

  float acc[4][8][4];
#pragma unroll
  for (int mt = 0; mt < 4; ++mt)
#pragma unroll
    for (int n8 = 0; n8 < 8; ++n8)
#pragma unroll
      for (int j = 0; j < 4; ++j) acc[mt][n8][j] = 0.f;

  float4 av[4];

  // ---- prologue: chunk 0 ----
#pragma unroll
  for (int i = 0; i < 4; ++i) {
    const int col = aseg + i * 4;
    av[i] = (col < I) ? *reinterpret_cast<const float4*>(xrow + col)
                      : make_float4(0.f, 0.f, 0.f, 0.f);
  }
  {
    const unsigned char* src = g_wB;                 // term 0, chunk 0
    const unsigned char* srcL = g_wB + (size_t)NCH * WIMG;
#pragma unroll
    for (int i = 0; i < 4; ++i) {
      CPASYNC16(sb + BHI + tid * 16 + i * 4096, src + tid * 16 + i * 4096);
      CPASYNC16(sb + BLO + tid * 16 + i * 4096, srcL + tid * 16 + i * 4096);
    }
    asm volatile("cp.async.commit_group;" ::: "memory");
  }
  // STS A chunk0 into stage 0
  {
#pragma unroll
    for (int half = 0; half < 2; ++half) {
      const float f[8] = {half ? av[2].x : av[0].x, half ? av[2].y : av[0].y,
                          half ? av[2].z : av[0].z, half ? av[2].w : av[0].w,
                          half ? av[3].x : av[1].x, half ? av[3].y : av[1].y,
                          half ? av[3].z : av[1].z, half ? av[3].w : av[1].w};
      // NOTE: elements must be in k order: av[0]=cols 0-3, av[1]=4-7 for half0
      const float g0 = half ? av[2].x : av[0].x;
      (void)g0;
      uint32_t hu[4], lu[4];
#pragma unroll
      for (int jj = 0; jj < 4; ++jj) {
        const float f0 = (half == 0) ? ((jj < 2) ? ((jj == 0) ? av[0].x : av[0].z)
                                                 : ((jj == 2) ? av[1].x : av[1].z))
                                     : ((jj < 2) ? ((jj == 0) ? av[2].x : av[2].z)
                                                 : ((jj == 2) ? av[3].x : av[3].z));
        const float f1 = (half == 0) ? ((jj < 2) ? ((jj == 0) ? av[0].y : av[0].w)
                                                 : ((jj == 2) ? av[1].y : av[1].w))
                                     : ((jj < 2) ? ((jj == 0) ? av[2].y : av[2].w)
                                                 : ((jj == 2) ? av[3].y : av[3].w));
        __nv_bfloat16 h0 = __float2bfloat16(f0), h1 = __float2bfloat16(f1);
        __nv_bfloat16 l0 = __float2bfloat16(f0 - __bfloat162float(h0));
        __nv_bfloat16 l1 = __float2bfloat16(f1 - __bfloat162float(h1));
        hu[jj] = (uint32_t)__bfloat16_as_ushort(h0) |
                 ((uint32_t)__bfloat16_as_ushort(h1) << 16);
        lu[jj] = (uint32_t)__bfloat16_as_ushort(l0) |
                 ((uint32_t)__bfloat16_as_ushort(l1) << 16);
      }
      const int cc = (aseg >> 3) + half;
      const uint32_t off = aDstBase + ((uint32_t)(cc ^ aXor) << 4);
      *reinterpret_cast<uint4*>(smem + AHI + off) = make_uint4(hu[0], hu[1], hu[2], hu[3]);
      *reinterpret_cast<uint4*>(smem + ALO + off) = make_uint4(lu[0], lu[1], lu[2], lu[3]);
    }
  }

  // ---- main loop over 22 chunks ----
  for (int c = 0; c < NCH; ++c) {
    asm volatile("cp.async.wait_group 0;" ::: "memory");
    __syncthreads();

    const int nc = c + 1;
    if (nc < NCH) {
      const uint32_t nst = sb + (nc & 1) * STAGE;
      const unsigned char* src = g_wB + (size_t)nc * WIMG;
      const unsigned char* srcL = g_wB + (size_t)(NCH + nc) * WIMG;
#pragma unroll
      for (int i = 0; i < 4; ++i) {
        CPASYNC16(nst + BHI + tid * 16 + i * 4096, src + tid * 16 + i * 4096);
        CPASYNC16(nst + BLO + tid * 16 + i * 4096, srcL + tid * 16 + i * 4096);
      }
      asm volatile("cp.async.commit_group;" ::: "memory");
      const int colbase = nc * 32 + aseg;
#pragma unroll
      for (int i = 0; i < 4; ++i) {
        const int col = colbase + i * 4;
        av[i] = (col < I) ? *reinterpret_cast<const float4*>(xrow + col)
                          : make_float4(0.f, 0.f, 0.f, 0.f);
      }
    }

    // ---- compute chunk c ----
    const uint32_t st = sb + (c & 1) * STAGE;
#pragma unroll
    for (int k16 = 0; k16 < 2; ++k16) {
      uint32_t ah[4][4], al[4][4], bb[4][4];
      const int kca = k16 * 2 + ca;
      const int kcb = k16 * 2 + cb;
#pragma unroll
      for (int mt = 0; mt < 4; ++mt)
        LDSM4(ah[mt], st + AHI + raddr[mt] + (((kca ^ sxa[mt])) << 4));
#pragma unroll
      for (int g = 0; g < 4; ++g)
        LDSM4(bb[g], st + BHI + rbad[g] + (((kcb ^ sxb[g])) << 4));
#pragma unroll
      for (int mt = 0; mt < 4; ++mt)
#pragma unroll
        for (int g = 0; g < 4; ++g) {
          MMA16816(acc[mt][2 * g], ah[mt], bb[g][0], bb[g][1]);
          MMA16816(acc[mt][2 * g + 1], ah[mt], bb[g][2], bb[g][3]);
        }
#pragma unroll
      for (int mt = 0; mt < 4; ++mt)
        LDSM4(al[mt], st + ALO + raddr[mt] + (((kca ^ sxa[mt])) << 4));
#pragma unroll
      for (int mt = 0; mt < 4; ++mt)
#pragma unroll
        for (int g = 0; g < 4; ++g) {
          MMA16816(acc[mt][2 * g], al[mt], bb[g][0], bb[g][1]);
          MMA16816(acc[mt][2 * g + 1], al[mt], bb[g][2], bb[g][3]);
        }
#pragma unroll
      for (int g = 0; g < 4; ++g)
        LDSM4(bb[g], st + BLO + rbad[g] + (((kcb ^ sxb[g])) << 4));
#pragma unroll
      for (int mt = 0; mt < 4; ++mt)
#pragma unroll
        for (int g = 0; g < 4; ++g) {
          MMA16816(acc[mt][2 * g], ah[mt], bb[g][0], bb[g][1]);
          MMA16816(acc[mt][2 * g + 1], ah[mt], bb[g][2], bb[g][3]);
        }
    }

    // ---- STS A(next) into the other stage ----
    if (nc < NCH) {
      unsigned char* stn = smem + (nc & 1) * STAGE;
#pragma unroll
      for (int half = 0; half < 2; ++half) {
        uint32_t hu[4], lu[4];
        const float4 p = half ? av[2] : av[0];
        const float4 q = half ? av[3] : av[1];
        const float fs[8] = {p.x, p.y, p.z, p.w, q.x, q.y, q.z, q.w};
#pragma unroll
        for (int jj = 0; jj < 4; ++jj) {
          __nv_bfloat16 h0 = __float2bfloat16(fs[2 * jj]);
          __nv_bfloat16 h1 = __float2bfloat16(fs[2 * jj + 1]);
          __nv_bfloat16 l0 = __float2bfloat16(fs[2 * jj] - __bfloat162float(h0));
          __nv_bfloat16 l1 = __float2bfloat16(fs[2 * jj + 1] - __bfloat162float(h1));
          hu[jj] = (uint32_t)__bfloat16_as_ushort(h0) |
                   ((uint32_t)__bfloat16_as_ushort(h1) << 16);
          lu[jj] = (uint32_t)__bfloat16_as_ushort(l0) |
                   ((uint32_t)__bfloat16_as_ushort(l1) << 16);
        }
        const int cc = (aseg >> 3) + half;
        const uint32_t off = aDstBase + ((uint32_t)(cc ^ aXor) << 4);
        *reinterpret_cast<uint4*>(stn + AHI + off) = make_uint4(hu[0], hu[1], hu[2], hu[3]);
        *reinterpret_cast<uint4*>(stn + ALO + off) = make_uint4(lu[0], lu[1], lu[2], lu[3]);
      }
    }
  }

  // ---- epilogue: acc -> g_curx ----
#pragma unroll
  for (int mt = 0; mt < 4; ++mt) {
    const int r0 = m0 + wm + mt * 16 + (lane >> 2);
#pragma unroll
    for (int n8 = 0; n8 < 8; ++n8) {
      const int col = wn + n8 * 8 + (lane & 3) * 2;
      *reinterpret_cast<float2*>(g_curx + (size_t)r0 * H + col) =
          make_float2(acc[mt][n8][0], acc[mt][n8][1]);
      *reinterpret_cast<float2*>(g_curx + (size_t)(r0 + 8) * H + col) =
          make_float2(acc[mt][n8][2], acc[mt][n8][3]);
    }
  }
}

// ---------------------------------------------------------------------------
// Kernel 2: persistent BRF recurrence (unchanged from round 3 — passing)
// ---------------------------------------------------------------------------
__global__ void __cluster_dims__(2, 1, 1) __launch_bounds__(256, 1)
rec_kernel(const float* __restrict__ Wh, const float* __restrict__ omp,
           const float* __restrict__ bop, const float* __restrict__ Wo,
           const float* __restrict__ taup, const int* __restrict__ Y,
           float* __restrict__ out) {
  extern __shared__ float sm[];
  float4* zb = reinterpret_cast<float4*>(sm + SM_ZB);
  float* Ws = sm + SM_WS;
  float* comb = sm + SM_COMB;
  float* WoT = sm + SM_WOT;
  float* pouA = sm + SM_POUA;
  float* pouB = sm + SM_POUB;
  float* ous = sm + SM_OUS;
  float* alph = sm + SM_AL;

  const int tid = threadIdx.x;
  unsigned rank;
  asm("mov.u32 %0, %%cluster_ctarank;" : "=r"(rank));
  const int cl = blockIdx.x >> 1, row0 = cl * 4;

  for (int i = tid; i < 32768; i += 256) {
    int j = i >> 7, hl = i & 127;
    Ws[i] = Wh[(size_t)((int)rank * 128 + hl) * WHS + I + j];
  }
  for (int i = tid; i < 2560; i += 256) {
    int hl = i / 20, o = i - hl * 20;
    WoT[i] = Wo[o * H + (int)rank * 128 + hl];
  }
  if (tid < O) alph[tid] = expf(-DELTA / taup[tid]);
  for (int i = tid; i < 512; i += 256) zb[i] = make_float4(0.f, 0.f, 0.f, 0.f);
  for (int i = tid; i < 160; i += 256) { pouA[i] = 0.f; pouB[i] = 0.f; }
  for (int i = tid; i < 80; i += 256) ous[i] = 0.f;

  const int h = tid & 127, half = tid >> 7;
  float om = 0.f, pom = 0.f, bof = 0.f;
  float u[4] = {0, 0, 0, 0}, v[4] = {0, 0, 0, 0}, q[4] = {0, 0, 0, 0},
        zr[4] = {0, 0, 0, 0};
  if (tid < 128) {
    int hg = (int)rank * 128 + tid;
    om = fabsf(omp[hg]);
    float dm = DELTA * om;
    pom = (-1.f + sqrtf(1.f - dm * dm)) / DELTA;
    bof = fabsf(bop[hg]);
  }
  float lossacc = 0.f;
  int yprev = 0;

  const unsigned zrem = mapa_rank(smem_u32(zb), rank ^ 1u);
  const unsigned prem = mapa_rank(smem_u32(pouB), 0u);

  __syncthreads();
  cluster_sync_all();

  for (int t = 0; t < T; ++t) {
    const int cb2 = t & 1, nb = cb2 ^ 1;

    if (rank == 0 && tid < 4) {
      int ynew = Y[t * B + row0 + tid];
      if (t > 0) {
        const int pb = cb2 ^ 1;
        const float* pa = pouA + pb * 80 + tid * 20;
        const float* pbp = pouB + pb * 80 + tid * 20;
        float m = -1e30f, ly = 0.f;
        for (int o = 0; o < O; ++o) {
          float a = alph[o];
          float s = ous[tid * 20 + o] * a + (1.f - a) * (pa[o] + pbp[o]);
          ous[tid * 20 + o] = s;
          out[(size_t)(t - 1) * B * O + (size_t)(row0 + tid) * O + o] = s;
          m = fmaxf(m, s);
          if (o == yprev) ly = s;
        }
        float se = 0.f;
        for (int o = 0; o < O; ++o) se += expf(ous[tid * 20 + o] - m);
        lossacc += -(ly - m - logf(se)) * (1.f / (float)B);
      }
      yprev = ynew;
    }

    float c0 = 0.f, c1 = 0.f, c2 = 0.f, c3 = 0.f;
    if (tid < 128) {
      const float* cp = g_curx + ((size_t)t * B + row0) * H + (int)rank * 128 + tid;
      c0 = cp[0]; c1 = cp[H]; c2 = cp[2 * H]; c3 = cp[3 * H];
    }

    float a0 = 0.f, a1 = 0.f, a2 = 0.f, a3 = 0.f;
    {
      const float4* zrow = zb + cb2 * 256 + half * 128;
      const float* wc = Ws + half * 128 * 128 + h;
#pragma unroll 16
      for (int j = 0; j < 128; ++j) {
        float w = wc[j * 128];
        float4 z4 = zrow[j];
        a0 += w * z4.x; a1 += w * z4.y; a2 += w * z4.z; a3 += w * z4.w;
      }
    }
    if (half) {
      comb[h] = a0; comb[128 + h] = a1; comb[256 + h] = a2; comb[384 + h] = a3;
    }
    __syncthreads();

    if (tid < 128) {
      float cw[4] = {c0 + a0 + comb[tid], c1 + a1 + comb[128 + tid],
                     c2 + a2 + comb[256 + tid], c3 + a3 + comb[384 + tid]};
#pragma unroll
      for (int rr = 0; rr < 4; ++rr) {
        float b = pom - bof - q[rr];
        float un = u[rr] + DELTA * (b * u[rr] - om * v[rr] + cw[rr]);
        float vn = v[rr] + DELTA * (om * un + b * v[rr]);
        float z = (un - THETA - q[rr]) > 0.f ? 1.f : 0.f;
        q[rr] = GAMMA * q[rr] + z;
        u[rr] = un; v[rr] = vn; zr[rr] = z;
      }
      int jg = (int)rank * 128 + tid;
      zb[nb * 256 + jg] = make_float4(zr[0], zr[1], zr[2], zr[3]);
      unsigned pa = zrem + (unsigned)(nb * 256 + jg) * 16u;
      stc_f32(pa, zr[0]); stc_f32(pa + 4, zr[1]);
      stc_f32(pa + 8, zr[2]); stc_f32(pa + 12, zr[3]);
    }
    __syncthreads();

    if (tid < 80) {
      int rr = tid / 20, o = tid - rr * 20;
      const float* zz = sm + SM_ZB + (size_t)(nb * 256 + (int)rank * 128) * 4 + rr;
      float s = 0.f;
#pragma unroll 8
      for (int jj = 0; jj < 128; ++jj) s += zz[jj * 4] * WoT[jj * 20 + o];
      if (rank == 0) pouA[cb2 * 80 + tid] = s;
      else stc_f32(prem + (unsigned)(cb2 * 80 + tid) * 4u, s);
    }

    cluster_sync_all();
  }

  if (rank == 0 && tid < 4) {
    const int pb = (T - 1) & 1;
    const float* pa = pouA + pb * 80 + tid * 20;
    const float* pbp = pouB + pb * 80 + tid * 20;
    float m = -1e30f, ly = 0.f;
    for (int o = 0; o < O; ++o) {
      float a = alph[o];
      float s = ous[tid * 20 + o] * a + (1.f - a) * (pa[o] + pbp[o]);
      ous[tid * 20 + o] = s;
      out[(size_t)(T - 1) * B * O + (size_t)(row0 + tid) * O + o] = s;
      m = fmaxf(m, s);
      if (o == yprev) ly = s;
    }
    float se = 0.f;
    for (int o = 0; o < O; ++o) se += expf(ous[tid * 20 + o] - m);
    lossacc += -(ly - m - logf(se)) * (1.f / (float)B);
    g_loss[row0 + tid] = lossacc;
  }
  __syncthreads();

  if (tid < 128) {
#pragma unroll
    for (int rr = 0; rr < 4; ++rr) {
      size_t idx = (size_t)(row0 + rr) * H + (int)rank * 128 + tid;
      out[OFF_ZF + idx] = zr[rr];
      out[OFF_UF + idx] = u[rr];
    }
  }
  if (rank == 0 && tid < 80) {
    int rr = tid / 20, o = tid - rr * 20;
    out[OFF_OUF + (size_t)(row0 + rr) * O + o] = ous[tid];
  }
}

// ---------------------------------------------------------------------------
// Kernel 3: deterministic loss reduction
// ---------------------------------------------------------------------------
__global__ void loss_sum_kernel(float* __restrict__ out) {
  __shared__ float s[256];
  s[threadIdx.x] = g_loss[threadIdx.x];
  __syncthreads();
  for (int st = 128; st > 0; st >>= 1) {
    if (threadIdx.x < st) s[threadIdx.x] += s[threadIdx.x + st];
    __syncthreads();
  }
  if (threadIdx.x == 0) out[OFF_LOSS] = s[0];
}

// ---------------------------------------------------------------------------
extern "C" void kernel_launch(void* const* d_in, const int* in_sizes, int n_in,
                              void* d_out, int out_size) {
  const float* x = (const float*)d_in[0];
  const int* y = (const int*)d_in[1];
  const float* Wh = (const float*)d_in[2];
  const float* omega = (const float*)d_in[3];
  const float* boff = (const float*)d_in[4];
  const float* Wo = (const float*)d_in[5];
  const float* tau = (const float*)d_in[6];
  float* out = (float*)d_out;

  cudaFuncSetAttribute(gemm_mma_kernel, cudaFuncAttributeMaxDynamicSharedMemorySize,
                       GS_TOTAL);
  cudaFuncSetAttribute(rec_kernel, cudaFuncAttributeMaxDynamicSharedMemorySize,
                       SM_TOT * (int)sizeof(float));

  prep_w_kernel<<<2 * NCH, 256>>>(Wh);
  gemm_mma_kernel<<<(T * B) / 128, 256, GS_TOTAL>>>(x);
  rec_kernel<<<B / 2, 256, SM_TOT * sizeof(float)>>>(Wh, omega, boff, Wo, tau, y, out);
  loss_sum_kernel<<<1, 256>>>(out);
}